// round 9
// baseline (speedup 1.0000x reference)
#include <cuda_runtime.h>
#include <cuda_bf16.h>
#include <math.h>

// Problem constants (fixed by the dataset)
#define B_   2
#define C_   64
#define E_   4
#define HLR_ 192
#define WLR_ 192
#define HHR_ 384
#define WHR_ 384
#define HWLR_ (HLR_*WLR_)
#define HWHR_ (HHR_*WHR_)

// Precomputed per-parity quantities (4 variants: hp*2+wp)
__device__ float g_wc[2][2][8][64];    // dynamic compress weights [hp][wp][j][c]
__device__ float g_we[2][2][64][8];    // dynamic expand weights   [hp][wp][c][j]
__device__ float g_offx[2][2], g_offy[2][2];   // raw offsets (fallback path)
__device__ int   g_fast[2];            // per-hp: fast window path valid
__device__ int   g_dyf[2];             // fast: shared y0 delta (rel. to byy)
__device__ int   g_dxmin[2];           // fast: window base delta (rel. to m)
__device__ int   g_ox[2][2];           // fast: per-q tap offset in window (0/1)
__device__ float g_wxf[2][2], g_wyf[2][2];     // fast: per-q fracs

// ---------------------------------------------------------------------------
// Kernel 0 (fast, from R7): 1 block x 1024 threads.
// ---------------------------------------------------------------------------
__global__ void __launch_bounds__(1024) precompute_kernel(
    const float* __restrict__ w1, const float* __restrict__ b1,
    const float* __restrict__ w2, const float* __restrict__ b2,
    const float* __restrict__ rw, const float* __restrict__ rb,
    const float* __restrict__ ow, const float* __restrict__ ob,
    const float* __restrict__ WC, const float* __restrict__ WE)
{
    __shared__ float s_e1[4][64];
    __shared__ float s_emb[4][64];
    __shared__ float s_rt[4][4];
    __shared__ float s_off[4][2];

    const int tid = threadIdx.x;

    if (tid < 256) {
        int v = tid >> 6, k = tid & 63;
        int hp = v >> 1, wp = v & 1;
        float ch = (hp + 0.5f) * 0.5f; ch = ch - floorf(ch + 0.001f) - 0.5f;
        float cw = (wp + 0.5f) * 0.5f; cw = cw - floorf(cw + 0.001f) - 0.5f;
        float4 wv = ((const float4*)w1)[k];
        float e1 = b1[k] + wv.x * 0.5f + wv.y * 0.5f + wv.z * ch + wv.w * cw;
        s_e1[v][k] = fmaxf(e1, 0.0f);
    }
    __syncthreads();

    {
        int v = tid >> 8, o = (tid >> 2) & 63, part = tid & 3;
        const float4* w2v = (const float4*)(w2 + o * 64 + part * 16);
        const float*  e1p = &s_e1[v][part * 16];
        float acc = 0.0f;
        #pragma unroll
        for (int t = 0; t < 4; t++) {
            float4 wv = w2v[t];
            acc += wv.x * e1p[t*4+0] + wv.y * e1p[t*4+1]
                 + wv.z * e1p[t*4+2] + wv.w * e1p[t*4+3];
        }
        acc += __shfl_xor_sync(0xFFFFFFFFu, acc, 1);
        acc += __shfl_xor_sync(0xFFFFFFFFu, acc, 2);
        if (part == 0) s_emb[v][o] = fmaxf(acc + b2[o], 0.0f);
    }
    __syncthreads();

    if (tid < 64) {
        int v = tid >> 4, e = (tid >> 2) & 3, part = tid & 3;
        const float4* rwv = (const float4*)(rw + e * 64 + part * 16);
        const float*  emp = &s_emb[v][part * 16];
        float acc = 0.0f;
        #pragma unroll
        for (int t = 0; t < 4; t++) {
            float4 wv = rwv[t];
            acc += wv.x * emp[t*4+0] + wv.y * emp[t*4+1]
                 + wv.z * emp[t*4+2] + wv.w * emp[t*4+3];
        }
        acc += __shfl_xor_sync(0xFFFFFFFFu, acc, 1);
        acc += __shfl_xor_sync(0xFFFFFFFFu, acc, 2);
        if (part == 0) s_rt[v][e] = 1.0f / (1.0f + expf(-(acc + rb[e])));
    } else if (tid < 96) {
        int idx = tid - 64;
        int v = idx >> 3, k = (idx >> 2) & 1, part = idx & 3;
        const float4* owv = (const float4*)(ow + k * 64 + part * 16);
        const float*  emp = &s_emb[v][part * 16];
        float acc = 0.0f;
        #pragma unroll
        for (int t = 0; t < 4; t++) {
            float4 wv = owv[t];
            acc += wv.x * emp[t*4+0] + wv.y * emp[t*4+1]
                 + wv.z * emp[t*4+2] + wv.w * emp[t*4+3];
        }
        acc += __shfl_xor_sync(0xFFFFFFFFu, acc, 1);
        acc += __shfl_xor_sync(0xFFFFFFFFu, acc, 2);
        if (part == 0) s_off[v][k] = acc + ob[k];
    }
    __syncthreads();

    if (tid < 2) {
        int hpp = tid;
        float ox0 = s_off[hpp*2 + 0][0], oy0 = s_off[hpp*2 + 0][1];
        float ox1 = s_off[hpp*2 + 1][0], oy1 = s_off[hpp*2 + 1][1];
        g_offx[hpp][0] = ox0; g_offx[hpp][1] = ox1;
        g_offy[hpp][0] = oy0; g_offy[hpp][1] = oy1;
        float tx0 = -0.25f + ox0;
        float tx1 =  0.25f + ox1;
        float tyb = (hpp + 0.5f) * 0.5f - 0.5f;
        float ty0 = tyb + oy0;
        float ty1 = tyb + oy1;
        float fx0 = floorf(tx0), fx1 = floorf(tx1);
        float fy0 = floorf(ty0), fy1 = floorf(ty1);
        int dx0 = (int)fx0, dx1 = (int)fx1;
        int dy0 = (int)fy0, dy1 = (int)fy1;
        g_fast[hpp] = (dy0 == dy1) && (abs(dx1 - dx0) <= 1);
        int dmn = min(dx0, dx1);
        g_dyf[hpp]   = dy0;
        g_dxmin[hpp] = dmn;
        g_ox[hpp][0] = dx0 - dmn;
        g_ox[hpp][1] = dx1 - dmn;
        g_wxf[hpp][0] = tx0 - fx0;  g_wxf[hpp][1] = tx1 - fx1;
        g_wyf[hpp][0] = ty0 - fy0;  g_wyf[hpp][1] = ty1 - fy1;
    }
    __syncthreads();

    {
        if (tid < 512) {
            int v = tid >> 7, r4 = tid & 127;
            float r0 = s_rt[v][0], r1 = s_rt[v][1], r2 = s_rt[v][2], r3 = s_rt[v][3];
            const float4* wc4 = (const float4*)WC;
            float4 a0 = wc4[0*128 + r4], a1 = wc4[1*128 + r4];
            float4 a2 = wc4[2*128 + r4], a3 = wc4[3*128 + r4];
            float4 o4;
            o4.x = r0*a0.x + r1*a1.x + r2*a2.x + r3*a3.x;
            o4.y = r0*a0.y + r1*a1.y + r2*a2.y + r3*a3.y;
            o4.z = r0*a0.z + r1*a1.z + r2*a2.z + r3*a3.z;
            o4.w = r0*a0.w + r1*a1.w + r2*a2.w + r3*a3.w;
            ((float4*)&g_wc[0][0][0][0])[v * 128 + r4] = o4;
        } else {
            int t = tid - 512;
            int v = t >> 7, r4 = t & 127;
            float r0 = s_rt[v][0], r1 = s_rt[v][1], r2 = s_rt[v][2], r3 = s_rt[v][3];
            const float4* we4 = (const float4*)WE;
            float4 a0 = we4[0*128 + r4], a1 = we4[1*128 + r4];
            float4 a2 = we4[2*128 + r4], a3 = we4[3*128 + r4];
            float4 o4;
            o4.x = r0*a0.x + r1*a1.x + r2*a2.x + r3*a3.x;
            o4.y = r0*a0.y + r1*a1.y + r2*a2.y + r3*a3.y;
            o4.z = r0*a0.z + r1*a1.z + r2*a2.z + r3*a3.z;
            o4.w = r0*a0.w + r1*a1.w + r2*a2.w + r3*a3.w;
            ((float4*)&g_we[0][0][0][0])[v * 128 + r4] = o4;
        }
    }
}

// ---------------------------------------------------------------------------
// Main kernel. Block = 512 threads = 16 warps.
//   Fast path: block-local staging of the two LR rows with vertical
//   pre-interpolation per w-parity into s_vb[2][64][72] (raw-aligned;
//   column shift applied at tap-read time), then 2 LDS taps per (q, channel).
//   s_vb is UNIONED with s_part/s_midf (both 36864B) -> 41KB static smem.
// grid = (WHR/128, HHR, B).
// ---------------------------------------------------------------------------
#define VB_STRIDE 72

__global__ void __launch_bounds__(512) upsample_main(
    const float* __restrict__ fused, float* __restrict__ out)
{
    __shared__ float s_wc[2][8][64];        // [q][j][c]
    __shared__ float s_we[2][64][8];        // [q][c][j]
    __shared__ float s_pool[9216];          // union: vb[2][64][72]  OR  part+midf

    float (*s_vb)[64][VB_STRIDE] = (float (*)[64][VB_STRIDE])s_pool;
    float* s_part = s_pool;                  // [j][g][q][m] 8*8*2*64 = 8192 floats
    float* s_midf = s_pool + 8192;           // [j][q][m]    8*2*64   = 1024 floats

    const int tid  = threadIdx.x;
    const int l    = tid & 31;
    const int ww   = tid >> 5;
    const int g    = ww & 7;
    const int half = ww >> 3;
    const int h    = blockIdx.y;
    const int hp   = h & 1;
    const int byy  = h >> 1;
    const int b    = blockIdx.z;
    const int mbase = blockIdx.x * 64;
    const int ml   = half * 32 + l;          // m within tile [0,64)
    const int m    = mbase + ml;             // LR column

    // Stage dynamic weights: 512 float4 (wc 256 + we 256), one per thread.
    {
        const float4* srcc = (const float4*)&g_wc[hp][0][0][0];
        const float4* srce = (const float4*)&g_we[hp][0][0][0];
        float4* dc = (float4*)&s_wc[0][0][0];
        float4* de = (float4*)&s_we[0][0][0];
        if (tid < 256) dc[tid] = srcc[tid];
        else           de[tid - 256] = srce[tid - 256];
    }

    const int fast = g_fast[hp];
    float fea[2][8];

    if (fast) {
        // ---- Stage: rows y0,y0+1, vertical interp per q, raw-aligned -----
        const int y0  = byy + g_dyf[hp];
        const bool yv0 = (y0 >= 0) && (y0 < HLR_);
        const bool yv1 = (y0 + 1 >= 0) && (y0 + 1 < HLR_);
        const int yc0 = min(max(y0, 0), HLR_ - 1);
        const int yc1 = min(max(y0 + 1, 0), HLR_ - 1);
        const float wyA = g_wyf[hp][0], wyB = g_wyf[hp][1];
        const int xbase  = mbase + g_dxmin[hp];
        const int xalign = (xbase >> 2) << 2;        // floor to multiple of 4

        // 1152 chunks: c = idx/18, cf4 = idx%18 ; x = xalign + 4*cf4 (+0..3)
        #pragma unroll
        for (int k = 0; k < 3; k++) {
            int idx = tid + k * 512;
            if (idx < 1152) {
                int c   = idx / 18;
                int cf4 = idx - c * 18;
                int x0i = xalign + cf4 * 4;
                const float* pc = fused + (size_t)(b * C_ + c) * HWLR_;
                float4 v0, v1;
                if (x0i >= 0 && x0i + 3 < WLR_) {
                    v0 = yv0 ? *(const float4*)(pc + yc0 * WLR_ + x0i)
                             : make_float4(0.f, 0.f, 0.f, 0.f);
                    v1 = yv1 ? *(const float4*)(pc + yc1 * WLR_ + x0i)
                             : make_float4(0.f, 0.f, 0.f, 0.f);
                } else {
                    float e0[4], e1[4];
                    #pragma unroll
                    for (int e = 0; e < 4; e++) {
                        int x = x0i + e;
                        bool xin = (x >= 0) && (x < WLR_);
                        int xcl = min(max(x, 0), WLR_ - 1);
                        e0[e] = (yv0 && xin) ? pc[yc0 * WLR_ + xcl] : 0.0f;
                        e1[e] = (yv1 && xin) ? pc[yc1 * WLR_ + xcl] : 0.0f;
                    }
                    v0 = make_float4(e0[0], e0[1], e0[2], e0[3]);
                    v1 = make_float4(e1[0], e1[1], e1[2], e1[3]);
                }
                float4 a, bb;
                a.x = v0.x + wyA * (v1.x - v0.x);
                a.y = v0.y + wyA * (v1.y - v0.y);
                a.z = v0.z + wyA * (v1.z - v0.z);
                a.w = v0.w + wyA * (v1.w - v0.w);
                bb.x = v0.x + wyB * (v1.x - v0.x);
                bb.y = v0.y + wyB * (v1.y - v0.y);
                bb.z = v0.z + wyB * (v1.z - v0.z);
                bb.w = v0.w + wyB * (v1.w - v0.w);
                *(float4*)&s_vb[0][c][cf4 * 4] = a;
                *(float4*)&s_vb[1][c][cf4 * 4] = bb;
            }
        }
        __syncthreads();

        // ---- Taps: 2 LDS per (q, channel), shift applied at read ---------
        const int off = xbase - xalign;              // 0..3
        const int t0 = off + g_ox[hp][0] + ml;
        const int t1 = off + g_ox[hp][1] + ml;
        const float wx0 = g_wxf[hp][0], wx1 = g_wxf[hp][1];
        #pragma unroll
        for (int i = 0; i < 8; i++) {
            const int c = g * 8 + i;
            float a0 = s_vb[0][c][t0], a1 = s_vb[0][c][t0 + 1];
            float b0 = s_vb[1][c][t1], b1 = s_vb[1][c][t1 + 1];
            fea[0][i] = a0 + wx0 * (a1 - a0);
            fea[1][i] = b0 + wx1 * (b1 - b0);
        }
        __syncthreads();   // all vb reads done before s_part overwrites pool
    } else {
        __syncthreads();   // match staging barrier count (uniform branch)
        // ---- generic fallback: independent 4-tap gather per parity -------
        const float* basep = fused + (size_t)(b * C_ + g * 8) * HWLR_;
        #pragma unroll
        for (int q = 0; q < 2; q++) {
            float px = (float)m + (q + 0.5f) * 0.5f - 0.5f + g_offx[hp][q];
            float py = (float)byy + (hp + 0.5f) * 0.5f - 0.5f + g_offy[hp][q];
            float x0f = floorf(px), y0f = floorf(py);
            float wx = px - x0f, wy = py - y0f;
            int x0 = (int)x0f, y0 = (int)y0f;
            bool vx0 = (x0 >= 0) && (x0 < WLR_);
            bool vx1 = (x0 + 1 >= 0) && (x0 + 1 < WLR_);
            bool vy0 = (y0 >= 0) && (y0 < HLR_);
            bool vy1 = (y0 + 1 >= 0) && (y0 + 1 < HLR_);
            float w00 = (vy0 && vx0) ? (1.0f - wx) * (1.0f - wy) : 0.0f;
            float w01 = (vy0 && vx1) ? wx * (1.0f - wy)          : 0.0f;
            float w10 = (vy1 && vx0) ? (1.0f - wx) * wy          : 0.0f;
            float w11 = (vy1 && vx1) ? wx * wy                   : 0.0f;
            int xc0 = min(max(x0, 0), WLR_ - 1);
            int xc1 = min(max(x0 + 1, 0), WLR_ - 1);
            int yc0 = min(max(y0, 0), HLR_ - 1);
            int yc1 = min(max(y0 + 1, 0), HLR_ - 1);
            #pragma unroll
            for (int i = 0; i < 8; i++) {
                const float* pl = basep + (size_t)i * HWLR_;
                const float* r0 = pl + yc0 * WLR_;
                const float* r1 = pl + yc1 * WLR_;
                fea[q][i] = r0[xc0] * w00 + r0[xc1] * w01
                          + r1[xc0] * w10 + r1[xc1] * w11;
            }
        }
        __syncthreads();   // match second staging barrier
    }

    // ---- Compress (8x8 matvec) for both parities ------------------------
    #pragma unroll
    for (int q = 0; q < 2; q++) {
        const float4* wc4 = (const float4*)&s_wc[q][0][g * 8];  // row stride 16 f4
        float4 fa = make_float4(fea[q][0], fea[q][1], fea[q][2], fea[q][3]);
        float4 fb = make_float4(fea[q][4], fea[q][5], fea[q][6], fea[q][7]);
        #pragma unroll
        for (int j = 0; j < 8; j++) {
            float4 wa = wc4[j * 16];
            float4 wb = wc4[j * 16 + 1];
            float a = wa.x * fa.x + wa.y * fa.y + wa.z * fa.z + wa.w * fa.w
                    + wb.x * fb.x + wb.y * fb.y + wb.z * fb.z + wb.w * fb.w;
            s_part[((j * 8 + g) * 2 + q) * 64 + ml] = a;
        }
    }
    __syncthreads();

    // ---- Reduce partials over channel groups: 16 warps <-> (j,q) --------
    {
        const int j = ww >> 1, qq = ww & 1;
        float s0 = 0.0f, s1 = 0.0f;
        #pragma unroll
        for (int gg = 0; gg < 8; gg++) {
            s0 += s_part[((j * 8 + gg) * 2 + qq) * 64 + l];
            s1 += s_part[((j * 8 + gg) * 2 + qq) * 64 + l + 32];
        }
        s_midf[(j * 2 + qq) * 64 + l]      = s0;
        s_midf[(j * 2 + qq) * 64 + l + 32] = s1;
    }
    __syncthreads();

    // ---- Expand + residual + contiguous float2 stores -------------------
    float mid0[8], mid1[8];
    #pragma unroll
    for (int j = 0; j < 8; j++) {
        mid0[j] = s_midf[(j * 2 + 0) * 64 + ml];
        mid1[j] = s_midf[(j * 2 + 1) * 64 + ml];
    }
    float* obp = out + ((size_t)(b * C_ + g * 8) * HHR_ + h) * WHR_ + 2 * m;
    #pragma unroll
    for (int i = 0; i < 8; i++) {
        const float4* we0 = (const float4*)&s_we[0][g * 8 + i][0];
        const float4* we1 = (const float4*)&s_we[1][g * 8 + i][0];
        float4 ea0 = we0[0], eb0 = we0[1];
        float4 ea1 = we1[0], eb1 = we1[1];
        float r0 = fea[0][i]
                 + ea0.x * mid0[0] + ea0.y * mid0[1] + ea0.z * mid0[2] + ea0.w * mid0[3]
                 + eb0.x * mid0[4] + eb0.y * mid0[5] + eb0.z * mid0[6] + eb0.w * mid0[7];
        float r1 = fea[1][i]
                 + ea1.x * mid1[0] + ea1.y * mid1[1] + ea1.z * mid1[2] + ea1.w * mid1[3]
                 + eb1.x * mid1[4] + eb1.y * mid1[5] + eb1.z * mid1[6] + eb1.w * mid1[7];
        float2 rv = make_float2(r0, r1);
        *(float2*)(obp + (size_t)i * HWHR_) = rv;
    }
}

// ---------------------------------------------------------------------------
extern "C" void kernel_launch(void* const* d_in, const int* in_sizes, int n_in,
                              void* d_out, int out_size)
{
    const float* fused = (const float*)d_in[1];
    const float* WC    = (const float*)d_in[2];
    const float* WE    = (const float*)d_in[3];
    const float* w1    = (const float*)d_in[4];
    const float* b1    = (const float*)d_in[5];
    const float* w2    = (const float*)d_in[6];
    const float* b2    = (const float*)d_in[7];
    const float* rw    = (const float*)d_in[8];
    const float* rb    = (const float*)d_in[9];
    const float* ow    = (const float*)d_in[10];
    const float* obv   = (const float*)d_in[11];
    float* out = (float*)d_out;

    precompute_kernel<<<1, 1024>>>(w1, b1, w2, b2, rw, rb, ow, obv, WC, WE);

    dim3 grid(WHR_ / 128, HHR_, B_);
    upsample_main<<<grid, 512>>>(fused, out);
}

// round 10
// speedup vs baseline: 1.2302x; 1.2302x over previous
#include <cuda_runtime.h>
#include <cuda_bf16.h>
#include <math.h>

// Problem constants (fixed by the dataset)
#define B_   2
#define C_   64
#define E_   4
#define HLR_ 192
#define WLR_ 192
#define HHR_ 384
#define WHR_ 384
#define HWLR_ (HLR_*WLR_)
#define HWHR_ (HHR_*WHR_)

// Precomputed per-parity quantities (4 variants: hp*2+wp)
__device__ float g_wc[2][2][8][64];    // dynamic compress weights [hp][wp][j][c]
__device__ float g_we[2][2][64][8];    // dynamic expand weights   [hp][wp][c][j]
__device__ float g_offx[2][2], g_offy[2][2];   // raw offsets (fallback path)
__device__ int   g_fast[2];            // per-hp: fast window path valid
__device__ int   g_dyf[2];             // fast: shared y0 delta (rel. to byy)
__device__ int   g_dxmin[2];           // fast: window base delta (rel. to m)
__device__ int   g_ox[2][2];           // fast: per-q tap offset in window (0/1)
__device__ float g_wxf[2][2], g_wyf[2][2];     // fast: per-q fracs

// ---------------------------------------------------------------------------
// Kernel 0 (fast, from R7): 1 block x 1024 threads.
// ---------------------------------------------------------------------------
__global__ void __launch_bounds__(1024) precompute_kernel(
    const float* __restrict__ w1, const float* __restrict__ b1,
    const float* __restrict__ w2, const float* __restrict__ b2,
    const float* __restrict__ rw, const float* __restrict__ rb,
    const float* __restrict__ ow, const float* __restrict__ ob,
    const float* __restrict__ WC, const float* __restrict__ WE)
{
    __shared__ float s_e1[4][64];
    __shared__ float s_emb[4][64];
    __shared__ float s_rt[4][4];
    __shared__ float s_off[4][2];

    const int tid = threadIdx.x;

    if (tid < 256) {
        int v = tid >> 6, k = tid & 63;
        int hp = v >> 1, wp = v & 1;
        float ch = (hp + 0.5f) * 0.5f; ch = ch - floorf(ch + 0.001f) - 0.5f;
        float cw = (wp + 0.5f) * 0.5f; cw = cw - floorf(cw + 0.001f) - 0.5f;
        float4 wv = ((const float4*)w1)[k];
        float e1 = b1[k] + wv.x * 0.5f + wv.y * 0.5f + wv.z * ch + wv.w * cw;
        s_e1[v][k] = fmaxf(e1, 0.0f);
    }
    __syncthreads();

    {
        int v = tid >> 8, o = (tid >> 2) & 63, part = tid & 3;
        const float4* w2v = (const float4*)(w2 + o * 64 + part * 16);
        const float*  e1p = &s_e1[v][part * 16];
        float acc = 0.0f;
        #pragma unroll
        for (int t = 0; t < 4; t++) {
            float4 wv = w2v[t];
            acc += wv.x * e1p[t*4+0] + wv.y * e1p[t*4+1]
                 + wv.z * e1p[t*4+2] + wv.w * e1p[t*4+3];
        }
        acc += __shfl_xor_sync(0xFFFFFFFFu, acc, 1);
        acc += __shfl_xor_sync(0xFFFFFFFFu, acc, 2);
        if (part == 0) s_emb[v][o] = fmaxf(acc + b2[o], 0.0f);
    }
    __syncthreads();

    if (tid < 64) {
        int v = tid >> 4, e = (tid >> 2) & 3, part = tid & 3;
        const float4* rwv = (const float4*)(rw + e * 64 + part * 16);
        const float*  emp = &s_emb[v][part * 16];
        float acc = 0.0f;
        #pragma unroll
        for (int t = 0; t < 4; t++) {
            float4 wv = rwv[t];
            acc += wv.x * emp[t*4+0] + wv.y * emp[t*4+1]
                 + wv.z * emp[t*4+2] + wv.w * emp[t*4+3];
        }
        acc += __shfl_xor_sync(0xFFFFFFFFu, acc, 1);
        acc += __shfl_xor_sync(0xFFFFFFFFu, acc, 2);
        if (part == 0) s_rt[v][e] = 1.0f / (1.0f + expf(-(acc + rb[e])));
    } else if (tid < 96) {
        int idx = tid - 64;
        int v = idx >> 3, k = (idx >> 2) & 1, part = idx & 3;
        const float4* owv = (const float4*)(ow + k * 64 + part * 16);
        const float*  emp = &s_emb[v][part * 16];
        float acc = 0.0f;
        #pragma unroll
        for (int t = 0; t < 4; t++) {
            float4 wv = owv[t];
            acc += wv.x * emp[t*4+0] + wv.y * emp[t*4+1]
                 + wv.z * emp[t*4+2] + wv.w * emp[t*4+3];
        }
        acc += __shfl_xor_sync(0xFFFFFFFFu, acc, 1);
        acc += __shfl_xor_sync(0xFFFFFFFFu, acc, 2);
        if (part == 0) s_off[v][k] = acc + ob[k];
    }
    __syncthreads();

    if (tid < 2) {
        int hpp = tid;
        float ox0 = s_off[hpp*2 + 0][0], oy0 = s_off[hpp*2 + 0][1];
        float ox1 = s_off[hpp*2 + 1][0], oy1 = s_off[hpp*2 + 1][1];
        g_offx[hpp][0] = ox0; g_offx[hpp][1] = ox1;
        g_offy[hpp][0] = oy0; g_offy[hpp][1] = oy1;
        float tx0 = -0.25f + ox0;
        float tx1 =  0.25f + ox1;
        float tyb = (hpp + 0.5f) * 0.5f - 0.5f;
        float ty0 = tyb + oy0;
        float ty1 = tyb + oy1;
        float fx0 = floorf(tx0), fx1 = floorf(tx1);
        float fy0 = floorf(ty0), fy1 = floorf(ty1);
        int dx0 = (int)fx0, dx1 = (int)fx1;
        int dy0 = (int)fy0, dy1 = (int)fy1;
        g_fast[hpp] = (dy0 == dy1) && (abs(dx1 - dx0) <= 1);
        int dmn = min(dx0, dx1);
        g_dyf[hpp]   = dy0;
        g_dxmin[hpp] = dmn;
        g_ox[hpp][0] = dx0 - dmn;
        g_ox[hpp][1] = dx1 - dmn;
        g_wxf[hpp][0] = tx0 - fx0;  g_wxf[hpp][1] = tx1 - fx1;
        g_wyf[hpp][0] = ty0 - fy0;  g_wyf[hpp][1] = ty1 - fy1;
    }
    __syncthreads();

    {
        if (tid < 512) {
            int v = tid >> 7, r4 = tid & 127;
            float r0 = s_rt[v][0], r1 = s_rt[v][1], r2 = s_rt[v][2], r3 = s_rt[v][3];
            const float4* wc4 = (const float4*)WC;
            float4 a0 = wc4[0*128 + r4], a1 = wc4[1*128 + r4];
            float4 a2 = wc4[2*128 + r4], a3 = wc4[3*128 + r4];
            float4 o4;
            o4.x = r0*a0.x + r1*a1.x + r2*a2.x + r3*a3.x;
            o4.y = r0*a0.y + r1*a1.y + r2*a2.y + r3*a3.y;
            o4.z = r0*a0.z + r1*a1.z + r2*a2.z + r3*a3.z;
            o4.w = r0*a0.w + r1*a1.w + r2*a2.w + r3*a3.w;
            ((float4*)&g_wc[0][0][0][0])[v * 128 + r4] = o4;
        } else {
            int t = tid - 512;
            int v = t >> 7, r4 = t & 127;
            float r0 = s_rt[v][0], r1 = s_rt[v][1], r2 = s_rt[v][2], r3 = s_rt[v][3];
            const float4* we4 = (const float4*)WE;
            float4 a0 = we4[0*128 + r4], a1 = we4[1*128 + r4];
            float4 a2 = we4[2*128 + r4], a3 = we4[3*128 + r4];
            float4 o4;
            o4.x = r0*a0.x + r1*a1.x + r2*a2.x + r3*a3.x;
            o4.y = r0*a0.y + r1*a1.y + r2*a2.y + r3*a3.y;
            o4.z = r0*a0.z + r1*a1.z + r2*a2.z + r3*a3.z;
            o4.w = r0*a0.w + r1*a1.w + r2*a2.w + r3*a3.w;
            ((float4*)&g_we[0][0][0][0])[v * 128 + r4] = o4;
        }
    }
}

// ---------------------------------------------------------------------------
// Main kernel. Block = 512 threads = 16 warps, forced 2 blocks/SM.
//   Fast path: block-local staging of the two LR rows with vertical
//   pre-interpolation per w-parity into s_vb[2][64][72] (raw-aligned), then
//   2 LDS taps per (q, channel). Staging uses one uniform scalar-predicated
//   path (low register pressure). s_vb is UNIONED with s_part/s_midf.
// grid = (WHR/128, HHR, B).
// ---------------------------------------------------------------------------
#define VB_STRIDE 72

__global__ void __launch_bounds__(512, 2) upsample_main(
    const float* __restrict__ fused, float* __restrict__ out)
{
    __shared__ float s_wc[2][8][64];        // [q][j][c]
    __shared__ float s_we[2][64][8];        // [q][c][j]
    __shared__ float s_pool[9216];          // union: vb[2][64][72]  OR  part+midf

    float (*s_vb)[64][VB_STRIDE] = (float (*)[64][VB_STRIDE])s_pool;
    float* s_part = s_pool;                  // [j][g][q][m] 8*8*2*64 = 8192 floats
    float* s_midf = s_pool + 8192;           // [j][q][m]    8*2*64   = 1024 floats

    const int tid  = threadIdx.x;
    const int l    = tid & 31;
    const int ww   = tid >> 5;
    const int g    = ww & 7;
    const int half = ww >> 3;
    const int h    = blockIdx.y;
    const int hp   = h & 1;
    const int byy  = h >> 1;
    const int b    = blockIdx.z;
    const int mbase = blockIdx.x * 64;
    const int ml   = half * 32 + l;          // m within tile [0,64)
    const int m    = mbase + ml;             // LR column

    // Stage dynamic weights: 512 float4 (wc 256 + we 256), one per thread.
    {
        const float4* srcc = (const float4*)&g_wc[hp][0][0][0];
        const float4* srce = (const float4*)&g_we[hp][0][0][0];
        float4* dc = (float4*)&s_wc[0][0][0];
        float4* de = (float4*)&s_we[0][0][0];
        if (tid < 256) dc[tid] = srcc[tid];
        else           de[tid - 256] = srce[tid - 256];
    }

    const int fast = g_fast[hp];
    float fea[2][8];

    if (fast) {
        // ---- Stage: rows y0,y0+1, vertical interp per q, raw-aligned -----
        const int y0  = byy + g_dyf[hp];
        const int yok0 = (y0 >= 0) && (y0 < HLR_);
        const int yok1 = (y0 + 1 >= 0) && (y0 + 1 < HLR_);
        const int yc0 = min(max(y0, 0), HLR_ - 1);
        const int yc1 = min(max(y0 + 1, 0), HLR_ - 1);
        const float wyA = g_wyf[hp][0], wyB = g_wyf[hp][1];
        const int xbase  = mbase + g_dxmin[hp];
        const int xalign = (xbase >> 2) << 2;        // floor to multiple of 4

        // 1152 chunks of 4 columns: c = idx/18, cf4 = idx%18
        #pragma unroll
        for (int k = 0; k < 3; k++) {
            int idx = tid + k * 512;
            if (idx < 1152) {
                int c   = idx / 18;
                int cf4 = idx - c * 18;
                int x0i = xalign + cf4 * 4;
                const float* pr0 = fused + (size_t)(b * C_ + c) * HWLR_ + yc0 * WLR_;
                const float* pr1 = pr0 + (yc1 - yc0) * WLR_;
                float4 a4, b4;
                float* ap = (float*)&a4;
                float* bp = (float*)&b4;
                #pragma unroll
                for (int e = 0; e < 4; e++) {
                    int x = x0i + e;
                    int xin = (x >= 0) && (x < WLR_);
                    int xcl = min(max(x, 0), WLR_ - 1);
                    float v0 = (yok0 && xin) ? pr0[xcl] : 0.0f;
                    float v1 = (yok1 && xin) ? pr1[xcl] : 0.0f;
                    float d = v1 - v0;
                    ap[e] = v0 + wyA * d;
                    bp[e] = v0 + wyB * d;
                }
                *(float4*)&s_vb[0][c][cf4 * 4] = a4;
                *(float4*)&s_vb[1][c][cf4 * 4] = b4;
            }
        }
        __syncthreads();

        // ---- Taps: 2 LDS per (q, channel), shift applied at read ---------
        const int off = xbase - xalign;              // 0..3
        const int t0 = off + g_ox[hp][0] + ml;
        const int t1 = off + g_ox[hp][1] + ml;
        const float wx0 = g_wxf[hp][0], wx1 = g_wxf[hp][1];
        #pragma unroll
        for (int i = 0; i < 8; i++) {
            const int c = g * 8 + i;
            float a0 = s_vb[0][c][t0], a1 = s_vb[0][c][t0 + 1];
            float b0 = s_vb[1][c][t1], b1 = s_vb[1][c][t1 + 1];
            fea[0][i] = a0 + wx0 * (a1 - a0);
            fea[1][i] = b0 + wx1 * (b1 - b0);
        }
        __syncthreads();   // all vb reads done before s_part overwrites pool
    } else {
        __syncthreads();   // match staging barrier count (uniform branch)
        // ---- generic fallback: independent 4-tap gather per parity -------
        const float* basep = fused + (size_t)(b * C_ + g * 8) * HWLR_;
        #pragma unroll
        for (int q = 0; q < 2; q++) {
            float px = (float)m + (q + 0.5f) * 0.5f - 0.5f + g_offx[hp][q];
            float py = (float)byy + (hp + 0.5f) * 0.5f - 0.5f + g_offy[hp][q];
            float x0f = floorf(px), y0f = floorf(py);
            float wx = px - x0f, wy = py - y0f;
            int x0 = (int)x0f, y0 = (int)y0f;
            bool vx0 = (x0 >= 0) && (x0 < WLR_);
            bool vx1 = (x0 + 1 >= 0) && (x0 + 1 < WLR_);
            bool vy0 = (y0 >= 0) && (y0 < HLR_);
            bool vy1 = (y0 + 1 >= 0) && (y0 + 1 < HLR_);
            float w00 = (vy0 && vx0) ? (1.0f - wx) * (1.0f - wy) : 0.0f;
            float w01 = (vy0 && vx1) ? wx * (1.0f - wy)          : 0.0f;
            float w10 = (vy1 && vx0) ? (1.0f - wx) * wy          : 0.0f;
            float w11 = (vy1 && vx1) ? wx * wy                   : 0.0f;
            int xc0 = min(max(x0, 0), WLR_ - 1);
            int xc1 = min(max(x0 + 1, 0), WLR_ - 1);
            int yc0 = min(max(y0, 0), HLR_ - 1);
            int yc1 = min(max(y0 + 1, 0), HLR_ - 1);
            #pragma unroll
            for (int i = 0; i < 8; i++) {
                const float* pl = basep + (size_t)i * HWLR_;
                const float* r0 = pl + yc0 * WLR_;
                const float* r1 = pl + yc1 * WLR_;
                fea[q][i] = r0[xc0] * w00 + r0[xc1] * w01
                          + r1[xc0] * w10 + r1[xc1] * w11;
            }
        }
        __syncthreads();   // match second staging barrier
    }

    // ---- Compress (8x8 matvec) for both parities ------------------------
    #pragma unroll
    for (int q = 0; q < 2; q++) {
        const float4* wc4 = (const float4*)&s_wc[q][0][g * 8];  // row stride 16 f4
        float4 fa = make_float4(fea[q][0], fea[q][1], fea[q][2], fea[q][3]);
        float4 fb = make_float4(fea[q][4], fea[q][5], fea[q][6], fea[q][7]);
        #pragma unroll
        for (int j = 0; j < 8; j++) {
            float4 wa = wc4[j * 16];
            float4 wb = wc4[j * 16 + 1];
            float a = wa.x * fa.x + wa.y * fa.y + wa.z * fa.z + wa.w * fa.w
                    + wb.x * fb.x + wb.y * fb.y + wb.z * fb.z + wb.w * fb.w;
            s_part[((j * 8 + g) * 2 + q) * 64 + ml] = a;
        }
    }
    __syncthreads();

    // ---- Reduce partials over channel groups: 16 warps <-> (j,q) --------
    {
        const int j = ww >> 1, qq = ww & 1;
        float s0 = 0.0f, s1 = 0.0f;
        #pragma unroll
        for (int gg = 0; gg < 8; gg++) {
            s0 += s_part[((j * 8 + gg) * 2 + qq) * 64 + l];
            s1 += s_part[((j * 8 + gg) * 2 + qq) * 64 + l + 32];
        }
        s_midf[(j * 2 + qq) * 64 + l]      = s0;
        s_midf[(j * 2 + qq) * 64 + l + 32] = s1;
    }
    __syncthreads();

    // ---- Expand + residual + contiguous float2 stores -------------------
    float mid0[8], mid1[8];
    #pragma unroll
    for (int j = 0; j < 8; j++) {
        mid0[j] = s_midf[(j * 2 + 0) * 64 + ml];
        mid1[j] = s_midf[(j * 2 + 1) * 64 + ml];
    }
    float* obp = out + ((size_t)(b * C_ + g * 8) * HHR_ + h) * WHR_ + 2 * m;
    #pragma unroll
    for (int i = 0; i < 8; i++) {
        const float4* we0 = (const float4*)&s_we[0][g * 8 + i][0];
        const float4* we1 = (const float4*)&s_we[1][g * 8 + i][0];
        float4 ea0 = we0[0], eb0 = we0[1];
        float4 ea1 = we1[0], eb1 = we1[1];
        float r0 = fea[0][i]
                 + ea0.x * mid0[0] + ea0.y * mid0[1] + ea0.z * mid0[2] + ea0.w * mid0[3]
                 + eb0.x * mid0[4] + eb0.y * mid0[5] + eb0.z * mid0[6] + eb0.w * mid0[7];
        float r1 = fea[1][i]
                 + ea1.x * mid1[0] + ea1.y * mid1[1] + ea1.z * mid1[2] + ea1.w * mid1[3]
                 + eb1.x * mid1[4] + eb1.y * mid1[5] + eb1.z * mid1[6] + eb1.w * mid1[7];
        float2 rv = make_float2(r0, r1);
        *(float2*)(obp + (size_t)i * HWHR_) = rv;
    }
}

// ---------------------------------------------------------------------------
extern "C" void kernel_launch(void* const* d_in, const int* in_sizes, int n_in,
                              void* d_out, int out_size)
{
    const float* fused = (const float*)d_in[1];
    const float* WC    = (const float*)d_in[2];
    const float* WE    = (const float*)d_in[3];
    const float* w1    = (const float*)d_in[4];
    const float* b1    = (const float*)d_in[5];
    const float* w2    = (const float*)d_in[6];
    const float* b2    = (const float*)d_in[7];
    const float* rw    = (const float*)d_in[8];
    const float* rb    = (const float*)d_in[9];
    const float* ow    = (const float*)d_in[10];
    const float* obv   = (const float*)d_in[11];
    float* out = (float*)d_out;

    precompute_kernel<<<1, 1024>>>(w1, b1, w2, b2, rw, rb, ow, obv, WC, WE);

    dim3 grid(WHR_ / 128, HHR_, B_);
    upsample_main<<<grid, 512>>>(fused, out);
}

// round 13
// speedup vs baseline: 1.4404x; 1.1709x over previous
#include <cuda_runtime.h>
#include <cuda_bf16.h>
#include <math.h>

// Problem constants (fixed by the dataset)
#define B_   2
#define C_   64
#define E_   4
#define HLR_ 192
#define WLR_ 192
#define HHR_ 384
#define WHR_ 384
#define HWLR_ (HLR_*WLR_)
#define HWHR_ (HHR_*WHR_)

// Precomputed per-parity quantities (4 variants: hp*2+wp)
__device__ float g_wc[2][2][8][64];    // dynamic compress weights [hp][wp][j][c]
__device__ float g_we[2][2][64][8];    // dynamic expand weights   [hp][wp][c][j]
__device__ float g_offx[2][2], g_offy[2][2];   // raw offsets (fallback path)
__device__ int   g_fast[2];            // per-hp: fast window path valid
__device__ int   g_dyf[2];             // fast: shared y0 delta (rel. to byy)
__device__ int   g_dxmin[2];           // fast: window base delta (rel. to m)
__device__ int   g_ox[2][2];           // fast: per-q tap offset in window (0/1)
__device__ float g_wxf[2][2], g_wyf[2][2];     // fast: per-q fracs

// ---------------------------------------------------------------------------
// Kernel 0 (fast, from R7): 1 block x 1024 threads.
// ---------------------------------------------------------------------------
__global__ void __launch_bounds__(1024) precompute_kernel(
    const float* __restrict__ w1, const float* __restrict__ b1,
    const float* __restrict__ w2, const float* __restrict__ b2,
    const float* __restrict__ rw, const float* __restrict__ rb,
    const float* __restrict__ ow, const float* __restrict__ ob,
    const float* __restrict__ WC, const float* __restrict__ WE)
{
    __shared__ float s_e1[4][64];
    __shared__ float s_emb[4][64];
    __shared__ float s_rt[4][4];
    __shared__ float s_off[4][2];

    const int tid = threadIdx.x;

    if (tid < 256) {
        int v = tid >> 6, k = tid & 63;
        int hp = v >> 1, wp = v & 1;
        float ch = (hp + 0.5f) * 0.5f; ch = ch - floorf(ch + 0.001f) - 0.5f;
        float cw = (wp + 0.5f) * 0.5f; cw = cw - floorf(cw + 0.001f) - 0.5f;
        float4 wv = ((const float4*)w1)[k];
        float e1 = b1[k] + wv.x * 0.5f + wv.y * 0.5f + wv.z * ch + wv.w * cw;
        s_e1[v][k] = fmaxf(e1, 0.0f);
    }
    __syncthreads();

    {
        int v = tid >> 8, o = (tid >> 2) & 63, part = tid & 3;
        const float4* w2v = (const float4*)(w2 + o * 64 + part * 16);
        const float*  e1p = &s_e1[v][part * 16];
        float acc = 0.0f;
        #pragma unroll
        for (int t = 0; t < 4; t++) {
            float4 wv = w2v[t];
            acc += wv.x * e1p[t*4+0] + wv.y * e1p[t*4+1]
                 + wv.z * e1p[t*4+2] + wv.w * e1p[t*4+3];
        }
        acc += __shfl_xor_sync(0xFFFFFFFFu, acc, 1);
        acc += __shfl_xor_sync(0xFFFFFFFFu, acc, 2);
        if (part == 0) s_emb[v][o] = fmaxf(acc + b2[o], 0.0f);
    }
    __syncthreads();

    if (tid < 64) {
        int v = tid >> 4, e = (tid >> 2) & 3, part = tid & 3;
        const float4* rwv = (const float4*)(rw + e * 64 + part * 16);
        const float*  emp = &s_emb[v][part * 16];
        float acc = 0.0f;
        #pragma unroll
        for (int t = 0; t < 4; t++) {
            float4 wv = rwv[t];
            acc += wv.x * emp[t*4+0] + wv.y * emp[t*4+1]
                 + wv.z * emp[t*4+2] + wv.w * emp[t*4+3];
        }
        acc += __shfl_xor_sync(0xFFFFFFFFu, acc, 1);
        acc += __shfl_xor_sync(0xFFFFFFFFu, acc, 2);
        if (part == 0) s_rt[v][e] = 1.0f / (1.0f + expf(-(acc + rb[e])));
    } else if (tid < 96) {
        int idx = tid - 64;
        int v = idx >> 3, k = (idx >> 2) & 1, part = idx & 3;
        const float4* owv = (const float4*)(ow + k * 64 + part * 16);
        const float*  emp = &s_emb[v][part * 16];
        float acc = 0.0f;
        #pragma unroll
        for (int t = 0; t < 4; t++) {
            float4 wv = owv[t];
            acc += wv.x * emp[t*4+0] + wv.y * emp[t*4+1]
                 + wv.z * emp[t*4+2] + wv.w * emp[t*4+3];
        }
        acc += __shfl_xor_sync(0xFFFFFFFFu, acc, 1);
        acc += __shfl_xor_sync(0xFFFFFFFFu, acc, 2);
        if (part == 0) s_off[v][k] = acc + ob[k];
    }
    __syncthreads();

    if (tid < 2) {
        int hpp = tid;
        float ox0 = s_off[hpp*2 + 0][0], oy0 = s_off[hpp*2 + 0][1];
        float ox1 = s_off[hpp*2 + 1][0], oy1 = s_off[hpp*2 + 1][1];
        g_offx[hpp][0] = ox0; g_offx[hpp][1] = ox1;
        g_offy[hpp][0] = oy0; g_offy[hpp][1] = oy1;
        float tx0 = -0.25f + ox0;
        float tx1 =  0.25f + ox1;
        float tyb = (hpp + 0.5f) * 0.5f - 0.5f;
        float ty0 = tyb + oy0;
        float ty1 = tyb + oy1;
        float fx0 = floorf(tx0), fx1 = floorf(tx1);
        float fy0 = floorf(ty0), fy1 = floorf(ty1);
        int dx0 = (int)fx0, dx1 = (int)fx1;
        int dy0 = (int)fy0, dy1 = (int)fy1;
        g_fast[hpp] = (dy0 == dy1) && (abs(dx1 - dx0) <= 1);
        int dmn = min(dx0, dx1);
        g_dyf[hpp]   = dy0;
        g_dxmin[hpp] = dmn;
        g_ox[hpp][0] = dx0 - dmn;
        g_ox[hpp][1] = dx1 - dmn;
        g_wxf[hpp][0] = tx0 - fx0;  g_wxf[hpp][1] = tx1 - fx1;
        g_wyf[hpp][0] = ty0 - fy0;  g_wyf[hpp][1] = ty1 - fy1;
    }
    __syncthreads();

    {
        if (tid < 512) {
            int v = tid >> 7, r4 = tid & 127;
            float r0 = s_rt[v][0], r1 = s_rt[v][1], r2 = s_rt[v][2], r3 = s_rt[v][3];
            const float4* wc4 = (const float4*)WC;
            float4 a0 = wc4[0*128 + r4], a1 = wc4[1*128 + r4];
            float4 a2 = wc4[2*128 + r4], a3 = wc4[3*128 + r4];
            float4 o4;
            o4.x = r0*a0.x + r1*a1.x + r2*a2.x + r3*a3.x;
            o4.y = r0*a0.y + r1*a1.y + r2*a2.y + r3*a3.y;
            o4.z = r0*a0.z + r1*a1.z + r2*a2.z + r3*a3.z;
            o4.w = r0*a0.w + r1*a1.w + r2*a2.w + r3*a3.w;
            ((float4*)&g_wc[0][0][0][0])[v * 128 + r4] = o4;
        } else {
            int t = tid - 512;
            int v = t >> 7, r4 = t & 127;
            float r0 = s_rt[v][0], r1 = s_rt[v][1], r2 = s_rt[v][2], r3 = s_rt[v][3];
            const float4* we4 = (const float4*)WE;
            float4 a0 = we4[0*128 + r4], a1 = we4[1*128 + r4];
            float4 a2 = we4[2*128 + r4], a3 = we4[3*128 + r4];
            float4 o4;
            o4.x = r0*a0.x + r1*a1.x + r2*a2.x + r3*a3.x;
            o4.y = r0*a0.y + r1*a1.y + r2*a2.y + r3*a3.y;
            o4.z = r0*a0.z + r1*a1.z + r2*a2.z + r3*a3.z;
            o4.w = r0*a0.w + r1*a1.w + r2*a2.w + r3*a3.w;
            ((float4*)&g_we[0][0][0][0])[v * 128 + r4] = o4;
        }
    }
}

// ---------------------------------------------------------------------------
// Main kernel (R8 body + gather-first reorder + float2 mid chain).
// Block = 512 threads = 16 warps, 2 blocks/SM.
//   warp ww: g = ww & 7 (channel group of 8), half = ww >> 3.
//   lane l -> LR column m = mbase + half*32 + l; thread produces BOTH
//   w-parities (HR cols w=2m, 2m+1): shared bilinear window, shared weights,
//   contiguous float2 stores.
// grid = (WHR/128, HHR, B).
// ---------------------------------------------------------------------------
__global__ void __launch_bounds__(512, 2) upsample_main(
    const float* __restrict__ fused, float* __restrict__ out)
{
    __shared__ float  s_wc[2][8][64];       // [q][j][c]
    __shared__ float  s_we[2][64][8];       // [q][c][j]
    __shared__ float2 s_part[8][8][64];     // [j][g][m] packed (q0,q1)
    __shared__ float2 s_midf[8][64];        // [j][m]    packed (q0,q1)

    const int tid  = threadIdx.x;
    const int l    = tid & 31;
    const int ww   = tid >> 5;
    const int g    = ww & 7;
    const int half = ww >> 3;
    const int h    = blockIdx.y;
    const int hp   = h & 1;
    const int byy  = h >> 1;
    const int b    = blockIdx.z;
    const int mbase = blockIdx.x * 64;
    const int ml   = half * 32 + l;          // m within tile [0,64)
    const int m    = mbase + ml;             // LR column

    const float* basep = fused + (size_t)(b * C_ + g * 8) * HWLR_;

    float fea[2][8];

    // ---- Gathers FIRST (no smem dependence): long-scoreboard latency
    //      overlaps with the weight staging below. ------------------------
    if (g_fast[hp]) {
        // ---- shared 2-row x 3-col window serving both parities ----------
        const int y0 = byy + g_dyf[hp];
        const int xg = m + g_dxmin[hp];
        const bool yv0 = (y0 >= 0) && (y0 < HLR_);
        const bool yv1 = (y0 + 1 >= 0) && (y0 + 1 < HLR_);
        const int yc0 = min(max(y0, 0), HLR_ - 1);
        const int yc1 = min(max(y0 + 1, 0), HLR_ - 1);
        const float wx0 = g_wxf[hp][0], wx1 = g_wxf[hp][1];
        const float wy0 = g_wyf[hp][0], wy1 = g_wyf[hp][1];
        const int o0 = g_ox[hp][0], o1 = g_ox[hp][1];

        bool xv[3]; int xc[3];
        #pragma unroll
        for (int k = 0; k < 3; k++) {
            int x = xg + k;
            xv[k] = (x >= 0) && (x < WLR_);
            xc[k] = min(max(x, 0), WLR_ - 1);
        }

        #pragma unroll
        for (int i = 0; i < 8; i++) {
            const float* pl = basep + (size_t)i * HWLR_;
            const float* r0 = pl + yc0 * WLR_;
            const float* r1 = pl + yc1 * WLR_;
            float u[3], vv[3];
            #pragma unroll
            for (int k = 0; k < 3; k++) {
                u[k]  = (yv0 && xv[k]) ? r0[xc[k]] : 0.0f;
                vv[k] = (yv1 && xv[k]) ? r1[xc[k]] : 0.0f;
            }
            {
                float ua = o0 ? u[1] : u[0],  ub = o0 ? u[2] : u[1];
                float va = o0 ? vv[1] : vv[0], vb = o0 ? vv[2] : vv[1];
                float top = ua * (1.0f - wx0) + ub * wx0;
                float bot = va * (1.0f - wx0) + vb * wx0;
                fea[0][i] = top * (1.0f - wy0) + bot * wy0;
            }
            {
                float ua = o1 ? u[1] : u[0],  ub = o1 ? u[2] : u[1];
                float va = o1 ? vv[1] : vv[0], vb = o1 ? vv[2] : vv[1];
                float top = ua * (1.0f - wx1) + ub * wx1;
                float bot = va * (1.0f - wx1) + vb * wx1;
                fea[1][i] = top * (1.0f - wy1) + bot * wy1;
            }
        }
    } else {
        // ---- generic fallback: independent 4-tap gather per parity -------
        #pragma unroll
        for (int q = 0; q < 2; q++) {
            float px = (float)m + (q + 0.5f) * 0.5f - 0.5f + g_offx[hp][q];
            float py = (float)byy + (hp + 0.5f) * 0.5f - 0.5f + g_offy[hp][q];
            float x0f = floorf(px), y0f = floorf(py);
            float wx = px - x0f, wy = py - y0f;
            int x0 = (int)x0f, y0 = (int)y0f;
            bool vx0 = (x0 >= 0) && (x0 < WLR_);
            bool vx1 = (x0 + 1 >= 0) && (x0 + 1 < WLR_);
            bool vy0 = (y0 >= 0) && (y0 < HLR_);
            bool vy1 = (y0 + 1 >= 0) && (y0 + 1 < HLR_);
            float w00 = (vy0 && vx0) ? (1.0f - wx) * (1.0f - wy) : 0.0f;
            float w01 = (vy0 && vx1) ? wx * (1.0f - wy)          : 0.0f;
            float w10 = (vy1 && vx0) ? (1.0f - wx) * wy          : 0.0f;
            float w11 = (vy1 && vx1) ? wx * wy                   : 0.0f;
            int xc0 = min(max(x0, 0), WLR_ - 1);
            int xc1 = min(max(x0 + 1, 0), WLR_ - 1);
            int yc0 = min(max(y0, 0), HLR_ - 1);
            int yc1 = min(max(y0 + 1, 0), HLR_ - 1);
            #pragma unroll
            for (int i = 0; i < 8; i++) {
                const float* pl = basep + (size_t)i * HWLR_;
                const float* r0 = pl + yc0 * WLR_;
                const float* r1 = pl + yc1 * WLR_;
                fea[q][i] = r0[xc0] * w00 + r0[xc1] * w01
                          + r1[xc0] * w10 + r1[xc1] * w11;
            }
        }
    }

    // ---- Stage dynamic weights (independent of gathers; fills the
    //      gather-latency shadow). 512 float4, one per thread. -------------
    {
        const float4* srcc = (const float4*)&g_wc[hp][0][0][0];
        const float4* srce = (const float4*)&g_we[hp][0][0][0];
        float4* dc = (float4*)&s_wc[0][0][0];
        float4* de = (float4*)&s_we[0][0][0];
        if (tid < 256) dc[tid] = srcc[tid];
        else           de[tid - 256] = srce[tid - 256];
    }
    __syncthreads();

    // ---- Compress (8x8 matvec), both parities packed as float2 ----------
    {
        const float4* wc40 = (const float4*)&s_wc[0][0][g * 8];  // stride 16 f4
        const float4* wc41 = (const float4*)&s_wc[1][0][g * 8];
        float4 fa0 = make_float4(fea[0][0], fea[0][1], fea[0][2], fea[0][3]);
        float4 fb0 = make_float4(fea[0][4], fea[0][5], fea[0][6], fea[0][7]);
        float4 fa1 = make_float4(fea[1][0], fea[1][1], fea[1][2], fea[1][3]);
        float4 fb1 = make_float4(fea[1][4], fea[1][5], fea[1][6], fea[1][7]);
        #pragma unroll
        for (int j = 0; j < 8; j++) {
            float4 wa0 = wc40[j * 16], wb0 = wc40[j * 16 + 1];
            float4 wa1 = wc41[j * 16], wb1 = wc41[j * 16 + 1];
            float a0 = wa0.x * fa0.x + wa0.y * fa0.y + wa0.z * fa0.z + wa0.w * fa0.w
                     + wb0.x * fb0.x + wb0.y * fb0.y + wb0.z * fb0.z + wb0.w * fb0.w;
            float a1 = wa1.x * fa1.x + wa1.y * fa1.y + wa1.z * fa1.z + wa1.w * fa1.w
                     + wb1.x * fb1.x + wb1.y * fb1.y + wb1.z * fb1.z + wb1.w * fb1.w;
            s_part[j][g][ml] = make_float2(a0, a1);
        }
    }
    __syncthreads();

    // ---- Reduce partials over channel groups: warp (j, seg) -------------
    {
        const int j = ww >> 1, seg = ww & 1;
        const int mm = seg * 32 + l;
        float sx = 0.0f, sy = 0.0f;
        #pragma unroll
        for (int gg = 0; gg < 8; gg++) {
            float2 p = s_part[j][gg][mm];
            sx += p.x; sy += p.y;
        }
        s_midf[j][mm] = make_float2(sx, sy);
    }
    __syncthreads();

    // ---- Expand + residual + contiguous float2 stores -------------------
    float mid0[8], mid1[8];
    #pragma unroll
    for (int j = 0; j < 8; j++) {
        float2 mv = s_midf[j][ml];
        mid0[j] = mv.x;
        mid1[j] = mv.y;
    }
    float* obp = out + ((size_t)(b * C_ + g * 8) * HHR_ + h) * WHR_ + 2 * m;
    #pragma unroll
    for (int i = 0; i < 8; i++) {
        const float4* we0 = (const float4*)&s_we[0][g * 8 + i][0];
        const float4* we1 = (const float4*)&s_we[1][g * 8 + i][0];
        float4 ea0 = we0[0], eb0 = we0[1];
        float4 ea1 = we1[0], eb1 = we1[1];
        float r0 = fea[0][i]
                 + ea0.x * mid0[0] + ea0.y * mid0[1] + ea0.z * mid0[2] + ea0.w * mid0[3]
                 + eb0.x * mid0[4] + eb0.y * mid0[5] + eb0.z * mid0[6] + eb0.w * mid0[7];
        float r1 = fea[1][i]
                 + ea1.x * mid1[0] + ea1.y * mid1[1] + ea1.z * mid1[2] + ea1.w * mid1[3]
                 + eb1.x * mid1[4] + eb1.y * mid1[5] + eb1.z * mid1[6] + eb1.w * mid1[7];
        float2 rv = make_float2(r0, r1);
        *(float2*)(obp + (size_t)i * HWHR_) = rv;
    }
}

// ---------------------------------------------------------------------------
extern "C" void kernel_launch(void* const* d_in, const int* in_sizes, int n_in,
                              void* d_out, int out_size)
{
    const float* fused = (const float*)d_in[1];
    const float* WC    = (const float*)d_in[2];
    const float* WE    = (const float*)d_in[3];
    const float* w1    = (const float*)d_in[4];
    const float* b1    = (const float*)d_in[5];
    const float* w2    = (const float*)d_in[6];
    const float* b2    = (const float*)d_in[7];
    const float* rw    = (const float*)d_in[8];
    const float* rb    = (const float*)d_in[9];
    const float* ow    = (const float*)d_in[10];
    const float* obv   = (const float*)d_in[11];
    float* out = (float*)d_out;

    precompute_kernel<<<1, 1024>>>(w1, b1, w2, b2, rw, rb, ow, obv, WC, WE);

    dim3 grid(WHR_ / 128, HHR_, B_);
    upsample_main<<<grid, 512>>>(fused, out);
}

// round 14
// speedup vs baseline: 1.5545x; 1.0792x over previous
#include <cuda_runtime.h>
#include <cuda_bf16.h>
#include <math.h>

// Problem constants (fixed by the dataset)
#define B_   2
#define C_   64
#define E_   4
#define HLR_ 192
#define WLR_ 192
#define HHR_ 384
#define WHR_ 384
#define HWLR_ (HLR_*WLR_)
#define HWHR_ (HHR_*WHR_)

// Precomputed per-parity quantities (4 variants: hp*2+wp)
__device__ float g_wc[2][2][8][64];    // dynamic compress weights [hp][wp][j][c]
__device__ float g_we[2][2][64][8];    // dynamic expand weights   [hp][wp][c][j]
__device__ float g_offx[2][2], g_offy[2][2];   // raw offsets (fallback path)
__device__ int   g_fast[2];            // per-hp: fast window path valid
__device__ int   g_dyf[2];             // fast: shared y0 delta (rel. to byy)
__device__ int   g_dxmin[2];           // fast: window base delta (rel. to m)
__device__ int   g_ox[2][2];           // fast: per-q tap offset in window (0/1)
__device__ float g_wxf[2][2], g_wyf[2][2];     // fast: per-q fracs

// ---------------------------------------------------------------------------
// Kernel 0 (fast, from R7): 1 block x 1024 threads.
// ---------------------------------------------------------------------------
__global__ void __launch_bounds__(1024) precompute_kernel(
    const float* __restrict__ w1, const float* __restrict__ b1,
    const float* __restrict__ w2, const float* __restrict__ b2,
    const float* __restrict__ rw, const float* __restrict__ rb,
    const float* __restrict__ ow, const float* __restrict__ ob,
    const float* __restrict__ WC, const float* __restrict__ WE)
{
    __shared__ float s_e1[4][64];
    __shared__ float s_emb[4][64];
    __shared__ float s_rt[4][4];
    __shared__ float s_off[4][2];

    const int tid = threadIdx.x;

    if (tid < 256) {
        int v = tid >> 6, k = tid & 63;
        int hp = v >> 1, wp = v & 1;
        float ch = (hp + 0.5f) * 0.5f; ch = ch - floorf(ch + 0.001f) - 0.5f;
        float cw = (wp + 0.5f) * 0.5f; cw = cw - floorf(cw + 0.001f) - 0.5f;
        float4 wv = ((const float4*)w1)[k];
        float e1 = b1[k] + wv.x * 0.5f + wv.y * 0.5f + wv.z * ch + wv.w * cw;
        s_e1[v][k] = fmaxf(e1, 0.0f);
    }
    __syncthreads();

    {
        int v = tid >> 8, o = (tid >> 2) & 63, part = tid & 3;
        const float4* w2v = (const float4*)(w2 + o * 64 + part * 16);
        const float*  e1p = &s_e1[v][part * 16];
        float acc = 0.0f;
        #pragma unroll
        for (int t = 0; t < 4; t++) {
            float4 wv = w2v[t];
            acc += wv.x * e1p[t*4+0] + wv.y * e1p[t*4+1]
                 + wv.z * e1p[t*4+2] + wv.w * e1p[t*4+3];
        }
        acc += __shfl_xor_sync(0xFFFFFFFFu, acc, 1);
        acc += __shfl_xor_sync(0xFFFFFFFFu, acc, 2);
        if (part == 0) s_emb[v][o] = fmaxf(acc + b2[o], 0.0f);
    }
    __syncthreads();

    if (tid < 64) {
        int v = tid >> 4, e = (tid >> 2) & 3, part = tid & 3;
        const float4* rwv = (const float4*)(rw + e * 64 + part * 16);
        const float*  emp = &s_emb[v][part * 16];
        float acc = 0.0f;
        #pragma unroll
        for (int t = 0; t < 4; t++) {
            float4 wv = rwv[t];
            acc += wv.x * emp[t*4+0] + wv.y * emp[t*4+1]
                 + wv.z * emp[t*4+2] + wv.w * emp[t*4+3];
        }
        acc += __shfl_xor_sync(0xFFFFFFFFu, acc, 1);
        acc += __shfl_xor_sync(0xFFFFFFFFu, acc, 2);
        if (part == 0) s_rt[v][e] = 1.0f / (1.0f + expf(-(acc + rb[e])));
    } else if (tid < 96) {
        int idx = tid - 64;
        int v = idx >> 3, k = (idx >> 2) & 1, part = idx & 3;
        const float4* owv = (const float4*)(ow + k * 64 + part * 16);
        const float*  emp = &s_emb[v][part * 16];
        float acc = 0.0f;
        #pragma unroll
        for (int t = 0; t < 4; t++) {
            float4 wv = owv[t];
            acc += wv.x * emp[t*4+0] + wv.y * emp[t*4+1]
                 + wv.z * emp[t*4+2] + wv.w * emp[t*4+3];
        }
        acc += __shfl_xor_sync(0xFFFFFFFFu, acc, 1);
        acc += __shfl_xor_sync(0xFFFFFFFFu, acc, 2);
        if (part == 0) s_off[v][k] = acc + ob[k];
    }
    __syncthreads();

    if (tid < 2) {
        int hpp = tid;
        float ox0 = s_off[hpp*2 + 0][0], oy0 = s_off[hpp*2 + 0][1];
        float ox1 = s_off[hpp*2 + 1][0], oy1 = s_off[hpp*2 + 1][1];
        g_offx[hpp][0] = ox0; g_offx[hpp][1] = ox1;
        g_offy[hpp][0] = oy0; g_offy[hpp][1] = oy1;
        float tx0 = -0.25f + ox0;
        float tx1 =  0.25f + ox1;
        float tyb = (hpp + 0.5f) * 0.5f - 0.5f;
        float ty0 = tyb + oy0;
        float ty1 = tyb + oy1;
        float fx0 = floorf(tx0), fx1 = floorf(tx1);
        float fy0 = floorf(ty0), fy1 = floorf(ty1);
        int dx0 = (int)fx0, dx1 = (int)fx1;
        int dy0 = (int)fy0, dy1 = (int)fy1;
        g_fast[hpp] = (dy0 == dy1) && (abs(dx1 - dx0) <= 1);
        int dmn = min(dx0, dx1);
        g_dyf[hpp]   = dy0;
        g_dxmin[hpp] = dmn;
        g_ox[hpp][0] = dx0 - dmn;
        g_ox[hpp][1] = dx1 - dmn;
        g_wxf[hpp][0] = tx0 - fx0;  g_wxf[hpp][1] = tx1 - fx1;
        g_wyf[hpp][0] = ty0 - fy0;  g_wyf[hpp][1] = ty1 - fy1;
    }
    __syncthreads();

    {
        if (tid < 512) {
            int v = tid >> 7, r4 = tid & 127;
            float r0 = s_rt[v][0], r1 = s_rt[v][1], r2 = s_rt[v][2], r3 = s_rt[v][3];
            const float4* wc4 = (const float4*)WC;
            float4 a0 = wc4[0*128 + r4], a1 = wc4[1*128 + r4];
            float4 a2 = wc4[2*128 + r4], a3 = wc4[3*128 + r4];
            float4 o4;
            o4.x = r0*a0.x + r1*a1.x + r2*a2.x + r3*a3.x;
            o4.y = r0*a0.y + r1*a1.y + r2*a2.y + r3*a3.y;
            o4.z = r0*a0.z + r1*a1.z + r2*a2.z + r3*a3.z;
            o4.w = r0*a0.w + r1*a1.w + r2*a2.w + r3*a3.w;
            ((float4*)&g_wc[0][0][0][0])[v * 128 + r4] = o4;
        } else {
            int t = tid - 512;
            int v = t >> 7, r4 = t & 127;
            float r0 = s_rt[v][0], r1 = s_rt[v][1], r2 = s_rt[v][2], r3 = s_rt[v][3];
            const float4* we4 = (const float4*)WE;
            float4 a0 = we4[0*128 + r4], a1 = we4[1*128 + r4];
            float4 a2 = we4[2*128 + r4], a3 = we4[3*128 + r4];
            float4 o4;
            o4.x = r0*a0.x + r1*a1.x + r2*a2.x + r3*a3.x;
            o4.y = r0*a0.y + r1*a1.y + r2*a2.y + r3*a3.y;
            o4.z = r0*a0.z + r1*a1.z + r2*a2.z + r3*a3.z;
            o4.w = r0*a0.w + r1*a1.w + r2*a2.w + r3*a3.w;
            ((float4*)&g_we[0][0][0][0])[v * 128 + r4] = o4;
        }
    }
}

// ---------------------------------------------------------------------------
// Main kernel (R13 dataflow, 256-thread blocks for 4 barrier domains/SM).
// Block = 256 threads = 8 warps; warp ww = channel group g, lane l = LR col.
// Each thread produces BOTH w-parities (HR cols w=2m, 2m+1).
// grid = (WHR/64, HHR, B); 4 blocks/SM (regs capped 64, smem 26KB).
// ---------------------------------------------------------------------------
__global__ void __launch_bounds__(256, 4) upsample_main(
    const float* __restrict__ fused, float* __restrict__ out)
{
    __shared__ float  s_wc[2][8][64];       // [q][j][c]
    __shared__ float  s_we[2][64][8];       // [q][c][j]
    __shared__ float2 s_part[8][8][32];     // [j][g][m] packed (q0,q1)
    __shared__ float2 s_midf[8][32];        // [j][m]    packed (q0,q1)

    const int tid  = threadIdx.x;
    const int l    = tid & 31;
    const int g    = tid >> 5;               // warp index == channel group
    const int h    = blockIdx.y;
    const int hp   = h & 1;
    const int byy  = h >> 1;
    const int b    = blockIdx.z;
    const int mbase = blockIdx.x * 32;
    const int m    = mbase + l;               // LR column

    const float* basep = fused + (size_t)(b * C_ + g * 8) * HWLR_;

    float fea[2][8];

    // ---- Gathers FIRST (no smem dependence): latency overlaps staging ----
    if (g_fast[hp]) {
        const int y0 = byy + g_dyf[hp];
        const int xg = m + g_dxmin[hp];
        const bool yv0 = (y0 >= 0) && (y0 < HLR_);
        const bool yv1 = (y0 + 1 >= 0) && (y0 + 1 < HLR_);
        const int yc0 = min(max(y0, 0), HLR_ - 1);
        const int yc1 = min(max(y0 + 1, 0), HLR_ - 1);
        const float wx0 = g_wxf[hp][0], wx1 = g_wxf[hp][1];
        const float wy0 = g_wyf[hp][0], wy1 = g_wyf[hp][1];
        const int o0 = g_ox[hp][0], o1 = g_ox[hp][1];

        bool xv[3]; int xc[3];
        #pragma unroll
        for (int k = 0; k < 3; k++) {
            int x = xg + k;
            xv[k] = (x >= 0) && (x < WLR_);
            xc[k] = min(max(x, 0), WLR_ - 1);
        }

        #pragma unroll
        for (int i = 0; i < 8; i++) {
            const float* pl = basep + (size_t)i * HWLR_;
            const float* r0 = pl + yc0 * WLR_;
            const float* r1 = pl + yc1 * WLR_;
            float u[3], vv[3];
            #pragma unroll
            for (int k = 0; k < 3; k++) {
                u[k]  = (yv0 && xv[k]) ? r0[xc[k]] : 0.0f;
                vv[k] = (yv1 && xv[k]) ? r1[xc[k]] : 0.0f;
            }
            {
                float ua = o0 ? u[1] : u[0],  ub = o0 ? u[2] : u[1];
                float va = o0 ? vv[1] : vv[0], vb = o0 ? vv[2] : vv[1];
                float top = ua * (1.0f - wx0) + ub * wx0;
                float bot = va * (1.0f - wx0) + vb * wx0;
                fea[0][i] = top * (1.0f - wy0) + bot * wy0;
            }
            {
                float ua = o1 ? u[1] : u[0],  ub = o1 ? u[2] : u[1];
                float va = o1 ? vv[1] : vv[0], vb = o1 ? vv[2] : vv[1];
                float top = ua * (1.0f - wx1) + ub * wx1;
                float bot = va * (1.0f - wx1) + vb * wx1;
                fea[1][i] = top * (1.0f - wy1) + bot * wy1;
            }
        }
    } else {
        #pragma unroll
        for (int q = 0; q < 2; q++) {
            float px = (float)m + (q + 0.5f) * 0.5f - 0.5f + g_offx[hp][q];
            float py = (float)byy + (hp + 0.5f) * 0.5f - 0.5f + g_offy[hp][q];
            float x0f = floorf(px), y0f = floorf(py);
            float wx = px - x0f, wy = py - y0f;
            int x0 = (int)x0f, y0 = (int)y0f;
            bool vx0 = (x0 >= 0) && (x0 < WLR_);
            bool vx1 = (x0 + 1 >= 0) && (x0 + 1 < WLR_);
            bool vy0 = (y0 >= 0) && (y0 < HLR_);
            bool vy1 = (y0 + 1 >= 0) && (y0 + 1 < HLR_);
            float w00 = (vy0 && vx0) ? (1.0f - wx) * (1.0f - wy) : 0.0f;
            float w01 = (vy0 && vx1) ? wx * (1.0f - wy)          : 0.0f;
            float w10 = (vy1 && vx0) ? (1.0f - wx) * wy          : 0.0f;
            float w11 = (vy1 && vx1) ? wx * wy                   : 0.0f;
            int xc0 = min(max(x0, 0), WLR_ - 1);
            int xc1 = min(max(x0 + 1, 0), WLR_ - 1);
            int yc0 = min(max(y0, 0), HLR_ - 1);
            int yc1 = min(max(y0 + 1, 0), HLR_ - 1);
            #pragma unroll
            for (int i = 0; i < 8; i++) {
                const float* pl = basep + (size_t)i * HWLR_;
                const float* r0 = pl + yc0 * WLR_;
                const float* r1 = pl + yc1 * WLR_;
                fea[q][i] = r0[xc0] * w00 + r0[xc1] * w01
                          + r1[xc0] * w10 + r1[xc1] * w11;
            }
        }
    }

    // ---- Stage dynamic weights (fills gather-latency shadow) -------------
    {
        const float4* srcc = (const float4*)&g_wc[hp][0][0][0];   // 256 f4
        const float4* srce = (const float4*)&g_we[hp][0][0][0];   // 256 f4
        ((float4*)&s_wc[0][0][0])[tid] = srcc[tid];
        ((float4*)&s_we[0][0][0])[tid] = srce[tid];
    }
    __syncthreads();

    // ---- Compress (8x8 matvec), both parities packed as float2 ----------
    {
        const float4* wc40 = (const float4*)&s_wc[0][0][g * 8];  // stride 16 f4
        const float4* wc41 = (const float4*)&s_wc[1][0][g * 8];
        float4 fa0 = make_float4(fea[0][0], fea[0][1], fea[0][2], fea[0][3]);
        float4 fb0 = make_float4(fea[0][4], fea[0][5], fea[0][6], fea[0][7]);
        float4 fa1 = make_float4(fea[1][0], fea[1][1], fea[1][2], fea[1][3]);
        float4 fb1 = make_float4(fea[1][4], fea[1][5], fea[1][6], fea[1][7]);
        #pragma unroll
        for (int j = 0; j < 8; j++) {
            float4 wa0 = wc40[j * 16], wb0 = wc40[j * 16 + 1];
            float4 wa1 = wc41[j * 16], wb1 = wc41[j * 16 + 1];
            float a0 = wa0.x * fa0.x + wa0.y * fa0.y + wa0.z * fa0.z + wa0.w * fa0.w
                     + wb0.x * fb0.x + wb0.y * fb0.y + wb0.z * fb0.z + wb0.w * fb0.w;
            float a1 = wa1.x * fa1.x + wa1.y * fa1.y + wa1.z * fa1.z + wa1.w * fa1.w
                     + wb1.x * fb1.x + wb1.y * fb1.y + wb1.z * fb1.z + wb1.w * fb1.w;
            s_part[j][g][l] = make_float2(a0, a1);
        }
    }
    __syncthreads();

    // ---- Reduce partials over channel groups: warp j -> midf[j][*] -------
    {
        const int j = g;                      // warp handles one j, all 32 m
        float sx = 0.0f, sy = 0.0f;
        #pragma unroll
        for (int gg = 0; gg < 8; gg++) {
            float2 p = s_part[j][gg][l];
            sx += p.x; sy += p.y;
        }
        s_midf[j][l] = make_float2(sx, sy);
    }
    __syncthreads();

    // ---- Expand + residual + contiguous float2 stores -------------------
    float mid0[8], mid1[8];
    #pragma unroll
    for (int j = 0; j < 8; j++) {
        float2 mv = s_midf[j][l];
        mid0[j] = mv.x;
        mid1[j] = mv.y;
    }
    float* obp = out + ((size_t)(b * C_ + g * 8) * HHR_ + h) * WHR_ + 2 * m;
    #pragma unroll
    for (int i = 0; i < 8; i++) {
        const float4* we0 = (const float4*)&s_we[0][g * 8 + i][0];
        const float4* we1 = (const float4*)&s_we[1][g * 8 + i][0];
        float4 ea0 = we0[0], eb0 = we0[1];
        float4 ea1 = we1[0], eb1 = we1[1];
        float r0 = fea[0][i]
                 + ea0.x * mid0[0] + ea0.y * mid0[1] + ea0.z * mid0[2] + ea0.w * mid0[3]
                 + eb0.x * mid0[4] + eb0.y * mid0[5] + eb0.z * mid0[6] + eb0.w * mid0[7];
        float r1 = fea[1][i]
                 + ea1.x * mid1[0] + ea1.y * mid1[1] + ea1.z * mid1[2] + ea1.w * mid1[3]
                 + eb1.x * mid1[4] + eb1.y * mid1[5] + eb1.z * mid1[6] + eb1.w * mid1[7];
        float2 rv = make_float2(r0, r1);
        *(float2*)(obp + (size_t)i * HWHR_) = rv;
    }
}

// ---------------------------------------------------------------------------
extern "C" void kernel_launch(void* const* d_in, const int* in_sizes, int n_in,
                              void* d_out, int out_size)
{
    const float* fused = (const float*)d_in[1];
    const float* WC    = (const float*)d_in[2];
    const float* WE    = (const float*)d_in[3];
    const float* w1    = (const float*)d_in[4];
    const float* b1    = (const float*)d_in[5];
    const float* w2    = (const float*)d_in[6];
    const float* b2    = (const float*)d_in[7];
    const float* rw    = (const float*)d_in[8];
    const float* rb    = (const float*)d_in[9];
    const float* ow    = (const float*)d_in[10];
    const float* obv   = (const float*)d_in[11];
    float* out = (float*)d_out;

    precompute_kernel<<<1, 1024>>>(w1, b1, w2, b2, rw, rb, ow, obv, WC, WE);

    dim3 grid(WHR_ / 64, HHR_, B_);
    upsample_main<<<grid, 256>>>(fused, out);
}